// round 7
// baseline (speedup 1.0000x reference)
#include <cuda_runtime.h>
#include <cuda_bf16.h>
#include <cstdint>

#define MAXN 50000
#define MAXE 800000
#define Hd   64
#define MAXK 16
#define NTGT (2 + MAXK)

// ---------------- device scratch (no allocs allowed) ----------------
static __device__ float    g_agg1[(size_t)MAXN * Hd]; // layer-1 agg (S1 rows only)
static __device__ float    g_h1[(size_t)MAXN * Hd];   // relu(conv1 out) (S1 rows only)
static __device__ int      g_is64;
static __device__ int      g_targets[NTGT];           // [curr, dest, nbr0..15]
static __device__ unsigned g_bitmap[(MAXN + 31) / 32];// membership of S1
static __device__ int      g_s1[MAXN];                // S1 node list
static __device__ int      g_ns1;
static __device__ int      g_elist2[MAXE];            // edges with dst in targets
static __device__ int      g_ne2;

// zero one agg1 row (done by the thread that first inserts the node into S1)
__device__ __forceinline__ void zero_agg1_row(int node) {
    float4* p = (float4*)(g_agg1 + (size_t)node * Hd);
    #pragma unroll
    for (int i = 0; i < 16; i++) p[i] = make_float4(0.f, 0.f, 0.f, 0.f);
}

// ---------------- prep: detect dtype, zero bitmap, seed S1 with targets ----
__global__ void k_prep(const void* ei, int E, long long N,
                       const void* curr, const void* dest, const void* nbr, int K) {
    int tid = threadIdx.x;
    if (tid == 0) {
        const long long* p = (const long long*)ei;
        int n = E < 8 ? E : 8;
        int ok = 1;
        for (int q = 0; q < n; q++) {
            long long v = p[q];
            if (v < 0 || v >= N) { ok = 0; break; }
        }
        g_is64 = ok;
        g_ne2 = 0; g_ns1 = 0;
    }
    __syncthreads();
    int is64 = g_is64;

    for (int i = tid; i < (MAXN + 31) / 32; i += blockDim.x) g_bitmap[i] = 0u;

    if (tid < NTGT) {
        int v = -1;
        if (tid == 0)       v = is64 ? (int)((const long long*)curr)[0] : ((const int*)curr)[0];
        else if (tid == 1)  v = is64 ? (int)((const long long*)dest)[0] : ((const int*)dest)[0];
        else if (tid < 2 + K)
            v = is64 ? (int)((const long long*)nbr)[tid - 2] : ((const int*)nbr)[tid - 2];
        g_targets[tid] = v;
    }
    __syncthreads();

    if (tid < 2 + K) {
        int v = g_targets[tid];
        unsigned bit = 1u << (v & 31);
        unsigned old = atomicOr(&g_bitmap[v >> 5], bit);
        if (!(old & bit)) {
            int sl = atomicAdd(&g_ns1, 1);
            g_s1[sl] = v;
            zero_agg1_row(v);
        }
    }
}

// ---------------- scan A: edges with dst in targets; grow S1 by src --------
__global__ void k_scanA(const void* __restrict__ ei, int E) {
    __shared__ int tg[NTGT];
    if (threadIdx.x < NTGT) tg[threadIdx.x] = g_targets[threadIdx.x];
    __syncthreads();

    int base = (blockIdx.x * blockDim.x + threadIdx.x) * 4;
    if (base >= E) return;
    int is64 = g_is64;

    int dv[4];
    int n = (base + 4 <= E) ? 4 : (E - base);
    if (n == 4 && (E & 3) == 0) {
        if (is64) {
            const long long* p = (const long long*)ei + E + base;
            longlong2 a = *(const longlong2*)p;
            longlong2 b = *(const longlong2*)(p + 2);
            dv[0] = (int)a.x; dv[1] = (int)a.y; dv[2] = (int)b.x; dv[3] = (int)b.y;
        } else {
            int4 a = *(const int4*)((const int*)ei + E + base);
            dv[0] = a.x; dv[1] = a.y; dv[2] = a.z; dv[3] = a.w;
        }
    } else {
        for (int j = 0; j < n; j++)
            dv[j] = is64 ? (int)((const long long*)ei)[E + base + j]
                         : ((const int*)ei)[E + base + j];
        for (int j = n; j < 4; j++) dv[j] = -1;
    }

    #pragma unroll
    for (int j = 0; j < 4; j++) {
        int d = dv[j];
        bool match = false;
        #pragma unroll
        for (int t = 0; t < NTGT; t++) match |= (d == tg[t]);
        if (!match) continue;
        int e = base + j;
        int pos = atomicAdd(&g_ne2, 1);
        g_elist2[pos] = e;
        int s = is64 ? (int)((const long long*)ei)[e] : ((const int*)ei)[e];
        unsigned bit = 1u << (s & 31);
        unsigned old = atomicOr(&g_bitmap[s >> 5], bit);
        if (!(old & bit)) {
            int sl = atomicAdd(&g_ns1, 1);
            g_s1[sl] = s;
            zero_agg1_row(s);
        }
    }
}

// ---------------- scan B + edge pass 1 fused --------------------------------
// Scan all dst; on S1-bitmap hit, compute 64-wide message and red.add inline.
__global__ void k_scanB(const float* __restrict__ x, const void* __restrict__ ei,
                        const float* __restrict__ ea, const float* __restrict__ We1,
                        const float* __restrict__ be1, int E) {
    int base = (blockIdx.x * blockDim.x + threadIdx.x) * 4;
    if (base >= E) return;
    int is64 = g_is64;

    int dv[4];
    int n = (base + 4 <= E) ? 4 : (E - base);
    if (n == 4 && (E & 3) == 0) {
        if (is64) {
            const long long* p = (const long long*)ei + E + base;
            longlong2 a = *(const longlong2*)p;
            longlong2 b = *(const longlong2*)(p + 2);
            dv[0] = (int)a.x; dv[1] = (int)a.y; dv[2] = (int)b.x; dv[3] = (int)b.y;
        } else {
            int4 a = *(const int4*)((const int*)ei + E + base);
            dv[0] = a.x; dv[1] = a.y; dv[2] = a.z; dv[3] = a.w;
        }
    } else {
        for (int j = 0; j < n; j++)
            dv[j] = is64 ? (int)((const long long*)ei)[E + base + j]
                         : ((const int*)ei)[E + base + j];
        for (int j = n; j < 4; j++) dv[j] = -1;
    }

    #pragma unroll
    for (int j = 0; j < 4; j++) {
        int d = dv[j];
        if (d < 0) continue;
        if (!((g_bitmap[d >> 5] >> (d & 31)) & 1u)) continue;
        int e = base + j;
        long long s = is64 ? ((const long long*)ei)[e] : (long long)((const int*)ei)[e];
        float a = __ldg(&ea[e]);
        const float4* xs = (const float4*)(x + s * Hd);
        float* dp = g_agg1 + (size_t)d * Hd;
        #pragma unroll
        for (int i = 0; i < 16; i++) {
            float4 xv = __ldg(xs + i);
            float4 wv = __ldg((const float4*)We1 + i);
            float4 bv = __ldg((const float4*)be1 + i);
            float4 m;
            m.x = fmaxf(xv.x + fmaf(a, wv.x, bv.x), 0.f);
            m.y = fmaxf(xv.y + fmaf(a, wv.y, bv.y), 0.f);
            m.z = fmaxf(xv.z + fmaf(a, wv.z, bv.z), 0.f);
            m.w = fmaxf(xv.w + fmaf(a, wv.w, bv.w), 0.f);
            asm volatile("red.global.add.v4.f32 [%0], {%1,%2,%3,%4};"
                         :: "l"(dp + 4 * i), "f"(m.x), "f"(m.y), "f"(m.z), "f"(m.w)
                         : "memory");
        }
    }
}

// ---------------- node MLP for layer 1 at S1 nodes only --------------------
#define NT 32
__global__ void __launch_bounds__(128) k_mlp1s(
        const float* __restrict__ x,
        const float* __restrict__ Wa, const float* __restrict__ ba,
        const float* __restrict__ Wb, const float* __restrict__ bb) {
    int ns1 = g_ns1;
    if ((long long)blockIdx.x * NT >= ns1) return;

    __shared__ __align__(16) float sWa[Hd * Hd];
    __shared__ __align__(16) float sWb[Hd * Hd];
    __shared__ __align__(16) float T[Hd * NT];
    __shared__ float sba[Hd], sbb[Hd];

    int tid = threadIdx.x;
    for (int i = tid * 4; i < Hd * Hd; i += 128 * 4) {
        *(float4*)&sWa[i] = *(const float4*)&Wa[i];
        *(float4*)&sWb[i] = *(const float4*)&Wb[i];
    }
    if (tid < Hd) { sba[tid] = ba[tid]; sbb[tid] = bb[tid]; }

    int ng = tid & 7;
    int jg = tid >> 3;

    for (int base = blockIdx.x * NT; base < ns1; base += gridDim.x * NT) {
        __syncthreads();
        {   // fill T = (x + agg1)^T for 32 S1 nodes
            int nn = tid >> 2;
            int idx = base + nn;
            int f0 = (tid & 3) * 16;
            if (idx < ns1) {
                size_t node = (size_t)g_s1[idx];
                const float4* xp = (const float4*)(x + node * Hd);
                const float4* ap = (const float4*)(g_agg1 + node * Hd);
                #pragma unroll
                for (int c = 0; c < 4; c++) {
                    float4 xv = xp[f0 / 4 + c];
                    float4 av = ap[f0 / 4 + c];
                    T[(f0 + 4 * c + 0) * NT + nn] = xv.x + av.x;
                    T[(f0 + 4 * c + 1) * NT + nn] = xv.y + av.y;
                    T[(f0 + 4 * c + 2) * NT + nn] = xv.z + av.z;
                    T[(f0 + 4 * c + 3) * NT + nn] = xv.w + av.w;
                }
            } else {
                #pragma unroll
                for (int c = 0; c < 16; c++) T[(f0 + c) * NT + nn] = 0.f;
            }
        }
        __syncthreads();

        float acc[4][4];
        #pragma unroll
        for (int a = 0; a < 4; a++)
            #pragma unroll
            for (int b = 0; b < 4; b++) acc[a][b] = 0.f;

        #pragma unroll
        for (int k = 0; k < Hd; k++) {
            float4 tf = *(const float4*)&T[k * NT + ng * 4];
            float4 wf = *(const float4*)&sWa[k * Hd + jg * 4];
            float tv[4] = {tf.x, tf.y, tf.z, tf.w};
            float wv[4] = {wf.x, wf.y, wf.z, wf.w};
            #pragma unroll
            for (int nn = 0; nn < 4; nn++)
                #pragma unroll
                for (int jj = 0; jj < 4; jj++)
                    acc[nn][jj] = fmaf(tv[nn], wv[jj], acc[nn][jj]);
        }
        __syncthreads();

        #pragma unroll
        for (int jj = 0; jj < 4; jj++) {
            float bv = sba[jg * 4 + jj];
            #pragma unroll
            for (int nn = 0; nn < 4; nn++)
                T[(jg * 4 + jj) * NT + ng * 4 + nn] = fmaxf(acc[nn][jj] + bv, 0.f);
        }
        __syncthreads();

        #pragma unroll
        for (int a = 0; a < 4; a++)
            #pragma unroll
            for (int b = 0; b < 4; b++) acc[a][b] = 0.f;

        #pragma unroll
        for (int k = 0; k < Hd; k++) {
            float4 tf = *(const float4*)&T[k * NT + ng * 4];
            float4 wf = *(const float4*)&sWb[k * Hd + jg * 4];
            float tv[4] = {tf.x, tf.y, tf.z, tf.w};
            float wv[4] = {wf.x, wf.y, wf.z, wf.w};
            #pragma unroll
            for (int nn = 0; nn < 4; nn++)
                #pragma unroll
                for (int jj = 0; jj < 4; jj++)
                    acc[nn][jj] = fmaf(tv[nn], wv[jj], acc[nn][jj]);
        }

        #pragma unroll
        for (int nn = 0; nn < 4; nn++) {
            int idx = base + ng * 4 + nn;
            if (idx < ns1) {
                size_t node = (size_t)g_s1[idx];
                float4 o;
                o.x = fmaxf(acc[nn][0] + sbb[jg * 4 + 0], 0.f);
                o.y = fmaxf(acc[nn][1] + sbb[jg * 4 + 1], 0.f);
                o.z = fmaxf(acc[nn][2] + sbb[jg * 4 + 2], 0.f);
                o.w = fmaxf(acc[nn][3] + sbb[jg * 4 + 3], 0.f);
                *(float4*)&g_h1[node * Hd + jg * 4] = o;
            }
        }
    }
}

// ---------------- fused: edge pass 2 (smem atomics) + layer-2 MLP + Q head --
__global__ void __launch_bounds__(256) k_final2(
        const void* __restrict__ ei, const float* __restrict__ ea,
        const float* __restrict__ We2, const float* __restrict__ be2,
        const float* __restrict__ W2a, const float* __restrict__ b2a,
        const float* __restrict__ W2b, const float* __restrict__ b2b,
        const float* __restrict__ Wl1, const float* __restrict__ bl1,
        const float* __restrict__ Wl2, const float* __restrict__ bl2,
        float* __restrict__ out, int E, int K) {
    __shared__ __align__(16) float w[Hd];
    __shared__ __align__(16) float b[Hd];
    __shared__ __align__(16) float sA[NTGT * Hd];   // agg2, then sT = h1+agg2
    __shared__ __align__(16) float sU[NTGT * Hd];
    __shared__ __align__(16) float sH2[NTGT * Hd];
    __shared__ __align__(16) float sZ[MAXK * Hd];
    __shared__ __align__(16) float cd[Hd];          // curr+dest part of lin1
    __shared__ int tg[NTGT];

    int tid = threadIdx.x;
    int nt = 2 + K;

    if (tid < NTGT) tg[tid] = g_targets[tid];
    if (tid < Hd) { w[tid] = We2[tid]; b[tid] = be2[tid]; }
    for (int i = tid; i < NTGT * Hd; i += 256) sA[i] = 0.f;
    __syncthreads();

    // ---- edge pass 2 over pre-filtered list, accumulate into smem ----
    int count = g_ne2;
    int is64 = g_is64;
    for (int idx = tid; idx < count * 16; idx += 256) {
        int e = g_elist2[idx >> 4];
        int l = idx & 15;
        int d;
        long long s;
        if (is64) {
            s = ((const long long*)ei)[e];
            d = (int)((const long long*)ei)[E + e];
        } else {
            s = (long long)((const int*)ei)[e];
            d = ((const int*)ei)[E + e];
        }
        float a = __ldg(&ea[e]);
        float4 xv = *((const float4*)(g_h1 + s * Hd) + l);
        float4 wv = ((const float4*)w)[l];
        float4 bv = ((const float4*)b)[l];
        float4 m;
        m.x = fmaxf(xv.x + fmaf(a, wv.x, bv.x), 0.f);
        m.y = fmaxf(xv.y + fmaf(a, wv.y, bv.y), 0.f);
        m.z = fmaxf(xv.z + fmaf(a, wv.z, bv.z), 0.f);
        m.w = fmaxf(xv.w + fmaf(a, wv.w, bv.w), 0.f);
        #pragma unroll
        for (int t = 0; t < NTGT; t++) {
            if (d == tg[t]) {
                float* base2 = &sA[t * Hd + l * 4];
                atomicAdd(base2 + 0, m.x);
                atomicAdd(base2 + 1, m.y);
                atomicAdd(base2 + 2, m.z);
                atomicAdd(base2 + 3, m.w);
            }
        }
    }
    __syncthreads();

    // ---- sT = h1[target] + agg2 (in place in sA) ----
    for (int i = tid; i < nt * Hd; i += 256) {
        int slot = i >> 6, j = i & 63;
        sA[i] += g_h1[(size_t)tg[slot] * Hd + j];
    }
    __syncthreads();

    // ---- mlp2 layer A ----
    for (int i = tid; i < nt * Hd; i += 256) {
        int slot = i >> 6, j = i & 63;
        float acc = b2a[j];
        const float* t = &sA[slot * Hd];
        #pragma unroll 8
        for (int k = 0; k < Hd; k++) acc = fmaf(t[k], __ldg(&W2a[k * Hd + j]), acc);
        sU[i] = fmaxf(acc, 0.f);
    }
    __syncthreads();

    // ---- mlp2 layer B (no relu) ----
    for (int i = tid; i < nt * Hd; i += 256) {
        int slot = i >> 6, j = i & 63;
        float acc = b2b[j];
        const float* u = &sU[slot * Hd];
        #pragma unroll 8
        for (int k = 0; k < Hd; k++) acc = fmaf(u[k], __ldg(&W2b[k * Hd + j]), acc);
        sH2[i] = acc;
    }
    __syncthreads();

    // ---- curr+dest part of lin1, computed once ----
    if (tid < Hd) {
        float acc = bl1[tid];
        #pragma unroll 8
        for (int t = 0; t < Hd; t++)
            acc = fmaf(sH2[t], __ldg(&Wl1[t * Hd + tid]), acc);
        #pragma unroll 8
        for (int t = 0; t < Hd; t++)
            acc = fmaf(sH2[Hd + t], __ldg(&Wl1[(Hd + t) * Hd + tid]), acc);
        cd[tid] = acc;
    }
    __syncthreads();

    // ---- lin1 per neighbor + relu ----
    for (int i = tid; i < K * Hd; i += 256) {
        int k = i >> 6, j = i & 63;
        float acc = cd[j];
        const float* nb = &sH2[(2 + k) * Hd];
        #pragma unroll 8
        for (int t = 0; t < Hd; t++)
            acc = fmaf(nb[t], __ldg(&Wl1[(2 * Hd + t) * Hd + j]), acc);
        sZ[i] = fmaxf(acc, 0.f);
    }
    __syncthreads();

    // ---- lin2 ----
    if (tid < K) {
        float acc = bl2[0];
        #pragma unroll 8
        for (int j = 0; j < Hd; j++) acc = fmaf(sZ[tid * Hd + j], Wl2[j], acc);
        out[tid] = acc;
    }
}

// ---------------- launcher ----------------
extern "C" void kernel_launch(void* const* d_in, const int* in_sizes, int n_in,
                              void* d_out, int out_size) {
    const float* x    = (const float*)d_in[0];
    const void*  ei   = d_in[1];
    const void*  curr = d_in[2];
    const void*  dest = d_in[3];
    const void*  nbr  = d_in[4];
    const float* ea   = (const float*)d_in[5];
    const float* We1  = (const float*)d_in[6];
    const float* be1  = (const float*)d_in[7];
    const float* W1a  = (const float*)d_in[8];
    const float* b1a  = (const float*)d_in[9];
    const float* W1b  = (const float*)d_in[10];
    const float* b1b  = (const float*)d_in[11];
    const float* We2  = (const float*)d_in[12];
    const float* be2  = (const float*)d_in[13];
    const float* W2a  = (const float*)d_in[14];
    const float* b2a  = (const float*)d_in[15];
    const float* W2b  = (const float*)d_in[16];
    const float* b2b  = (const float*)d_in[17];
    const float* Wl1  = (const float*)d_in[18];
    const float* bl1  = (const float*)d_in[19];
    const float* Wl2  = (const float*)d_in[20];
    const float* bl2  = (const float*)d_in[21];

    int N = in_sizes[0] / Hd;
    int E = in_sizes[5];
    int K = in_sizes[4];
    if (K > MAXK) K = MAXK;

    int scan_blocks = (E + 1023) / 1024;   // 4 edges per thread, 256 threads

    k_prep<<<1, 256>>>(ei, E, (long long)N, curr, dest, nbr, K);
    k_scanA<<<scan_blocks, 256>>>(ei, E);
    k_scanB<<<scan_blocks, 256>>>(x, ei, ea, We1, be1, E);
    k_mlp1s<<<32, 128>>>(x, W1a, b1a, W1b, b1b);
    k_final2<<<1, 256>>>(ei, ea, We2, be2, W2a, b2a, W2b, b2b,
                         Wl1, bl1, Wl2, bl2, (float*)d_out, E, K);
}

// round 8
// speedup vs baseline: 1.2682x; 1.2682x over previous
#include <cuda_runtime.h>
#include <cuda_bf16.h>
#include <cstdint>

#define MAXN 50000
#define MAXE 800000
#define Hd   64
#define MAXK 16
#define NTGT (2 + MAXK)

// ---------------- device scratch (no allocs allowed) ----------------
static __device__ float    g_agg1[(size_t)MAXN * Hd]; // layer-1 agg (S1 rows only)
static __device__ float    g_h1[(size_t)MAXN * Hd];   // relu(conv1 out) (S1 rows only)
static __device__ int      g_is64;
static __device__ int      g_targets[NTGT];           // [curr, dest, nbr0..15]
static __device__ unsigned g_bitmap[(MAXN + 31) / 32];// membership of S1
static __device__ int      g_s1[MAXN];                // S1 node list
static __device__ int      g_ns1;
static __device__ int      g_elist2[MAXE];            // edges with dst in targets
static __device__ int      g_ne2;

// zero one agg1 row (done by the thread that first inserts the node into S1)
__device__ __forceinline__ void zero_agg1_row(int node) {
    float4* p = (float4*)(g_agg1 + (size_t)node * Hd);
    #pragma unroll
    for (int i = 0; i < 16; i++) p[i] = make_float4(0.f, 0.f, 0.f, 0.f);
}

// ---------------- prep: detect dtype, zero bitmap, seed S1 with targets ----
__global__ void k_prep(const void* ei, int E, long long N,
                       const void* curr, const void* dest, const void* nbr, int K) {
    int tid = threadIdx.x;
    if (tid == 0) {
        const long long* p = (const long long*)ei;
        int n = E < 8 ? E : 8;
        int ok = 1;
        for (int q = 0; q < n; q++) {
            long long v = p[q];
            if (v < 0 || v >= N) { ok = 0; break; }
        }
        g_is64 = ok;
        g_ne2 = 0; g_ns1 = 0;
    }
    __syncthreads();
    int is64 = g_is64;

    for (int i = tid; i < (MAXN + 31) / 32; i += blockDim.x) g_bitmap[i] = 0u;

    if (tid < NTGT) {
        int v = -1;
        if (tid == 0)       v = is64 ? (int)((const long long*)curr)[0] : ((const int*)curr)[0];
        else if (tid == 1)  v = is64 ? (int)((const long long*)dest)[0] : ((const int*)dest)[0];
        else if (tid < 2 + K)
            v = is64 ? (int)((const long long*)nbr)[tid - 2] : ((const int*)nbr)[tid - 2];
        g_targets[tid] = v;
    }
    __syncthreads();

    if (tid < 2 + K) {
        int v = g_targets[tid];
        unsigned bit = 1u << (v & 31);
        unsigned old = atomicOr(&g_bitmap[v >> 5], bit);
        if (!(old & bit)) {
            int sl = atomicAdd(&g_ns1, 1);
            g_s1[sl] = v;
            zero_agg1_row(v);
        }
    }
}

// ---------------- scan A: edges with dst in targets; grow S1 by src --------
__global__ void k_scanA(const void* __restrict__ ei, int E) {
    __shared__ int tg[NTGT];
    if (threadIdx.x < NTGT) tg[threadIdx.x] = g_targets[threadIdx.x];
    __syncthreads();

    int base = (blockIdx.x * blockDim.x + threadIdx.x) * 4;
    if (base >= E) return;
    int is64 = g_is64;

    int dv[4];
    int n = (base + 4 <= E) ? 4 : (E - base);
    if (n == 4 && (E & 3) == 0) {
        if (is64) {
            const long long* p = (const long long*)ei + E + base;
            longlong2 a = *(const longlong2*)p;
            longlong2 b = *(const longlong2*)(p + 2);
            dv[0] = (int)a.x; dv[1] = (int)a.y; dv[2] = (int)b.x; dv[3] = (int)b.y;
        } else {
            int4 a = *(const int4*)((const int*)ei + E + base);
            dv[0] = a.x; dv[1] = a.y; dv[2] = a.z; dv[3] = a.w;
        }
    } else {
        for (int j = 0; j < n; j++)
            dv[j] = is64 ? (int)((const long long*)ei)[E + base + j]
                         : ((const int*)ei)[E + base + j];
        for (int j = n; j < 4; j++) dv[j] = -1;
    }

    #pragma unroll
    for (int j = 0; j < 4; j++) {
        int d = dv[j];
        bool match = false;
        #pragma unroll
        for (int t = 0; t < NTGT; t++) match |= (d == tg[t]);
        if (!match) continue;
        int e = base + j;
        int pos = atomicAdd(&g_ne2, 1);
        g_elist2[pos] = e;
        int s = is64 ? (int)((const long long*)ei)[e] : ((const int*)ei)[e];
        unsigned bit = 1u << (s & 31);
        unsigned old = atomicOr(&g_bitmap[s >> 5], bit);
        if (!(old & bit)) {
            int sl = atomicAdd(&g_ns1, 1);
            g_s1[sl] = s;
            zero_agg1_row(s);
        }
    }
}

// ---------------- scan B + edge pass 1, warp-cooperative --------------------
// Scan all dst; ballot hits; whole warp builds each hit's 64-wide message
// (lane l handles features 2l, 2l+1) and red.v2's it into g_agg1.
__global__ void k_scanB(const float* __restrict__ x, const void* __restrict__ ei,
                        const float* __restrict__ ea, const float* __restrict__ We1,
                        const float* __restrict__ be1, int E) {
    int lane = threadIdx.x & 31;
    int base = (blockIdx.x * blockDim.x + threadIdx.x) * 4;
    int is64 = g_is64;

    // per-lane weight/bias slice (registers)
    float2 wv = *((const float2*)We1 + lane);
    float2 bv = *((const float2*)be1 + lane);

    int dv[4];
    if (base < E) {
        int n = (base + 4 <= E) ? 4 : (E - base);
        if (n == 4 && (E & 3) == 0) {
            if (is64) {
                const long long* p = (const long long*)ei + E + base;
                longlong2 a = *(const longlong2*)p;
                longlong2 b = *(const longlong2*)(p + 2);
                dv[0] = (int)a.x; dv[1] = (int)a.y; dv[2] = (int)b.x; dv[3] = (int)b.y;
            } else {
                int4 a = *(const int4*)((const int*)ei + E + base);
                dv[0] = a.x; dv[1] = a.y; dv[2] = a.z; dv[3] = a.w;
            }
        } else {
            for (int j = 0; j < n; j++)
                dv[j] = is64 ? (int)((const long long*)ei)[E + base + j]
                             : ((const int*)ei)[E + base + j];
            for (int j = n; j < 4; j++) dv[j] = -1;
        }
    } else {
        dv[0] = dv[1] = dv[2] = dv[3] = -1;
    }

    #pragma unroll
    for (int j = 0; j < 4; j++) {
        int d = dv[j];
        bool hit = (d >= 0) && ((g_bitmap[d >> 5] >> (d & 31)) & 1u);
        unsigned m = __ballot_sync(0xffffffffu, hit);
        while (m) {
            int src_lane = __ffs(m) - 1;
            m &= m - 1;
            int e  = __shfl_sync(0xffffffffu, base + j, src_lane);
            int dd = __shfl_sync(0xffffffffu, d, src_lane);
            long long s = is64 ? ((const long long*)ei)[e]
                               : (long long)((const int*)ei)[e];
            float a = __ldg(&ea[e]);
            float2 xv = *((const float2*)(x + s * Hd) + lane);
            float m0 = fmaxf(xv.x + fmaf(a, wv.x, bv.x), 0.f);
            float m1 = fmaxf(xv.y + fmaf(a, wv.y, bv.y), 0.f);
            float* dp = g_agg1 + (size_t)dd * Hd + 2 * lane;
            asm volatile("red.global.add.v2.f32 [%0], {%1,%2};"
                         :: "l"(dp), "f"(m0), "f"(m1) : "memory");
        }
    }
}

// ---------------- node MLP for layer 1 at S1 nodes (lean version) ----------
// 4 nodes per block-iter, 256 threads: thread = (node n = tid/64, feature j).
// Weights streamed from global (L1/L2 resident), inputs staged in 1KB smem.
__global__ void __launch_bounds__(256) k_mlp1v2(
        const float* __restrict__ x,
        const float* __restrict__ Wa, const float* __restrict__ ba,
        const float* __restrict__ Wb, const float* __restrict__ bb) {
    __shared__ __align__(16) float sIn[4 * Hd];
    __shared__ __align__(16) float sU[4 * Hd];

    int tid = threadIdx.x;
    int nl  = tid >> 6;          // node slot within block: 0..3
    int j   = tid & 63;          // output feature
    int ns1 = g_ns1;

    for (int base = blockIdx.x * 4; base < ns1; base += gridDim.x * 4) {
        int idx = base + nl;
        bool valid = (idx < ns1);

        // stage input row: in = x[node] + agg1[node]
        if (valid) {
            size_t node = (size_t)g_s1[idx];
            sIn[tid] = x[node * Hd + j] + g_agg1[node * Hd + j];
        } else {
            sIn[tid] = 0.f;
        }
        __syncthreads();

        // GEMM1: u = relu(in @ Wa + ba)
        {
            float acc = __ldg(&ba[j]);
            const float* in = &sIn[nl * Hd];
            #pragma unroll 16
            for (int k = 0; k < Hd; k++)
                acc = fmaf(in[k], __ldg(&Wa[k * Hd + j]), acc);
            sU[tid] = fmaxf(acc, 0.f);
        }
        __syncthreads();

        // GEMM2: h1 = relu(u @ Wb + bb)
        {
            float acc = __ldg(&bb[j]);
            const float* u = &sU[nl * Hd];
            #pragma unroll 16
            for (int k = 0; k < Hd; k++)
                acc = fmaf(u[k], __ldg(&Wb[k * Hd + j]), acc);
            if (valid) {
                size_t node = (size_t)g_s1[idx];
                g_h1[node * Hd + j] = fmaxf(acc, 0.f);
            }
        }
        __syncthreads();
    }
}

// ---------------- fused: edge pass 2 (smem atomics) + layer-2 MLP + Q head --
__global__ void __launch_bounds__(512) k_final2(
        const void* __restrict__ ei, const float* __restrict__ ea,
        const float* __restrict__ We2, const float* __restrict__ be2,
        const float* __restrict__ W2a, const float* __restrict__ b2a,
        const float* __restrict__ W2b, const float* __restrict__ b2b,
        const float* __restrict__ Wl1, const float* __restrict__ bl1,
        const float* __restrict__ Wl2, const float* __restrict__ bl2,
        float* __restrict__ out, int E, int K) {
    __shared__ __align__(16) float w[Hd];
    __shared__ __align__(16) float b[Hd];
    __shared__ __align__(16) float sA[NTGT * Hd];   // agg2, then sT = h1+agg2
    __shared__ __align__(16) float sU[NTGT * Hd];
    __shared__ __align__(16) float sH2[NTGT * Hd];
    __shared__ __align__(16) float sZ[MAXK * Hd];
    __shared__ __align__(16) float cd[Hd];          // curr+dest part of lin1
    __shared__ int tg[NTGT];

    int tid = threadIdx.x;
    int nt = 2 + K;

    if (tid < NTGT) tg[tid] = g_targets[tid];
    if (tid < Hd) { w[tid] = We2[tid]; b[tid] = be2[tid]; }
    for (int i = tid; i < NTGT * Hd; i += 512) sA[i] = 0.f;
    __syncthreads();

    // ---- edge pass 2 over pre-filtered list, accumulate into smem ----
    int count = g_ne2;
    int is64 = g_is64;
    for (int idx = tid; idx < count * 16; idx += 512) {
        int e = g_elist2[idx >> 4];
        int l = idx & 15;
        int d;
        long long s;
        if (is64) {
            s = ((const long long*)ei)[e];
            d = (int)((const long long*)ei)[E + e];
        } else {
            s = (long long)((const int*)ei)[e];
            d = ((const int*)ei)[E + e];
        }
        float a = __ldg(&ea[e]);
        float4 xv = *((const float4*)(g_h1 + s * Hd) + l);
        float4 wv = ((const float4*)w)[l];
        float4 bv = ((const float4*)b)[l];
        float4 m;
        m.x = fmaxf(xv.x + fmaf(a, wv.x, bv.x), 0.f);
        m.y = fmaxf(xv.y + fmaf(a, wv.y, bv.y), 0.f);
        m.z = fmaxf(xv.z + fmaf(a, wv.z, bv.z), 0.f);
        m.w = fmaxf(xv.w + fmaf(a, wv.w, bv.w), 0.f);
        #pragma unroll
        for (int t = 0; t < NTGT; t++) {
            if (d == tg[t]) {
                float* base2 = &sA[t * Hd + l * 4];
                atomicAdd(base2 + 0, m.x);
                atomicAdd(base2 + 1, m.y);
                atomicAdd(base2 + 2, m.z);
                atomicAdd(base2 + 3, m.w);
            }
        }
    }
    __syncthreads();

    // ---- sT = h1[target] + agg2 (in place in sA) ----
    for (int i = tid; i < nt * Hd; i += 512) {
        int slot = i >> 6, j = i & 63;
        sA[i] += g_h1[(size_t)tg[slot] * Hd + j];
    }
    __syncthreads();

    // ---- mlp2 layer A ----
    for (int i = tid; i < nt * Hd; i += 512) {
        int slot = i >> 6, j = i & 63;
        float acc = b2a[j];
        const float* t = &sA[slot * Hd];
        #pragma unroll 8
        for (int k = 0; k < Hd; k++) acc = fmaf(t[k], __ldg(&W2a[k * Hd + j]), acc);
        sU[i] = fmaxf(acc, 0.f);
    }
    __syncthreads();

    // ---- mlp2 layer B (no relu) ----
    for (int i = tid; i < nt * Hd; i += 512) {
        int slot = i >> 6, j = i & 63;
        float acc = b2b[j];
        const float* u = &sU[slot * Hd];
        #pragma unroll 8
        for (int k = 0; k < Hd; k++) acc = fmaf(u[k], __ldg(&W2b[k * Hd + j]), acc);
        sH2[i] = acc;
    }
    __syncthreads();

    // ---- curr+dest part of lin1, computed once ----
    if (tid < Hd) {
        float acc = bl1[tid];
        #pragma unroll 8
        for (int t = 0; t < Hd; t++)
            acc = fmaf(sH2[t], __ldg(&Wl1[t * Hd + tid]), acc);
        #pragma unroll 8
        for (int t = 0; t < Hd; t++)
            acc = fmaf(sH2[Hd + t], __ldg(&Wl1[(Hd + t) * Hd + tid]), acc);
        cd[tid] = acc;
    }
    __syncthreads();

    // ---- lin1 per neighbor + relu ----
    for (int i = tid; i < K * Hd; i += 512) {
        int k = i >> 6, j = i & 63;
        float acc = cd[j];
        const float* nb = &sH2[(2 + k) * Hd];
        #pragma unroll 8
        for (int t = 0; t < Hd; t++)
            acc = fmaf(nb[t], __ldg(&Wl1[(2 * Hd + t) * Hd + j]), acc);
        sZ[i] = fmaxf(acc, 0.f);
    }
    __syncthreads();

    // ---- lin2 ----
    if (tid < K) {
        float acc = bl2[0];
        #pragma unroll 8
        for (int j = 0; j < Hd; j++) acc = fmaf(sZ[tid * Hd + j], Wl2[j], acc);
        out[tid] = acc;
    }
}

// ---------------- launcher ----------------
extern "C" void kernel_launch(void* const* d_in, const int* in_sizes, int n_in,
                              void* d_out, int out_size) {
    const float* x    = (const float*)d_in[0];
    const void*  ei   = d_in[1];
    const void*  curr = d_in[2];
    const void*  dest = d_in[3];
    const void*  nbr  = d_in[4];
    const float* ea   = (const float*)d_in[5];
    const float* We1  = (const float*)d_in[6];
    const float* be1  = (const float*)d_in[7];
    const float* W1a  = (const float*)d_in[8];
    const float* b1a  = (const float*)d_in[9];
    const float* W1b  = (const float*)d_in[10];
    const float* b1b  = (const float*)d_in[11];
    const float* We2  = (const float*)d_in[12];
    const float* be2  = (const float*)d_in[13];
    const float* W2a  = (const float*)d_in[14];
    const float* b2a  = (const float*)d_in[15];
    const float* W2b  = (const float*)d_in[16];
    const float* b2b  = (const float*)d_in[17];
    const float* Wl1  = (const float*)d_in[18];
    const float* bl1  = (const float*)d_in[19];
    const float* Wl2  = (const float*)d_in[20];
    const float* bl2  = (const float*)d_in[21];

    int N = in_sizes[0] / Hd;
    int E = in_sizes[5];
    int K = in_sizes[4];
    if (K > MAXK) K = MAXK;

    int scan_blocks = (E + 1023) / 1024;   // 4 edges per thread, 256 threads

    k_prep<<<1, 256>>>(ei, E, (long long)N, curr, dest, nbr, K);
    k_scanA<<<scan_blocks, 256>>>(ei, E);
    k_scanB<<<scan_blocks, 256>>>(x, ei, ea, We1, be1, E);
    k_mlp1v2<<<64, 256>>>(x, W1a, b1a, W1b, b1b);
    k_final2<<<1, 512>>>(ei, ea, We2, be2, W2a, b2a, W2b, b2b,
                         Wl1, bl1, Wl2, bl2, (float*)d_out, E, K);
}